// round 8
// baseline (speedup 1.0000x reference)
#include <cuda_runtime.h>
#include <cstdint>

#define HIDDEN   5120
#define NEXP     160
#define NGROUP   8
#define EPG      20
#define TOPK     6

#define BM       128
#define BK       16
#define NCHUNK   (HIDDEN / BK)   // 320
#define NTHREADS 256
#define LSTR     161

#define A_HALF   8192
#define A_BYTES  16384
#define B_HALF   10240
#define CHUNK_BYTES 36864
#define SMEM_BYTES (BM * LSTR * 4)   // 82432 >= 2*CHUNK_BYTES (73728)

#define NEG_INF (-__int_as_float(0x7f800000))
#define DELTA   1e-4f

// ---- device scratch for the rescue pass (static globals: allowed) ----
__device__ int g_count;
__device__ int g_list[16384];

__device__ __forceinline__ void mma_tf32(float* d, const uint32_t* a,
                                         uint32_t b0, uint32_t b1) {
    asm volatile(
        "mma.sync.aligned.m16n8k8.row.col.f32.tf32.tf32.f32 "
        "{%0,%1,%2,%3},{%4,%5,%6,%7},{%8,%9},{%0,%1,%2,%3};"
        : "+f"(d[0]), "+f"(d[1]), "+f"(d[2]), "+f"(d[3])
        : "r"(a[0]), "r"(a[1]), "r"(a[2]), "r"(a[3]), "r"(b0), "r"(b1));
}

__device__ __forceinline__ void split_tf32(float v, float& hf, float& lf) {
    uint32_t h;
    asm("cvt.rna.tf32.f32 %0, %1;" : "=r"(h) : "f"(v));
    hf = __uint_as_float(h);
    const float lo = v - hf;
    uint32_t l;
    asm("cvt.rna.tf32.f32 %0, %1;" : "=r"(l) : "f"(lo));
    lf = __uint_as_float(l);
}

__device__ __forceinline__ void stage_f4A(char* buf, int row, int q, float4 v) {
    char* tb = buf + (q >> 1) * A_HALF + (row >> 4) * 1024;
    const int r4 = ((((row & 15) >> 3)) + ((q & 1) << 1)) * 4;
    const int lbase = (row & 7) * 4;
    float e[4] = {v.x, v.y, v.z, v.w};
#pragma unroll
    for (int t = 0; t < 4; t++) {
        float hf, lo;
        split_tf32(e[t], hf, lo);
        char* p = tb + (lbase + t) * 16 + r4;
        *(float*)p = hf;
        *(float*)(p + 512) = lo;
    }
}

__device__ __forceinline__ void stage_f4B(char* buf, int n, int q, float4 v) {
    char* tb = buf + A_BYTES + (q >> 1) * B_HALF + (n >> 3) * 512;
    const int r4 = (q & 1) * 4;
    const int lbase = (n & 7) * 4;
    float e[4] = {v.x, v.y, v.z, v.w};
#pragma unroll
    for (int t = 0; t < 4; t++) {
        float hf, lo;
        split_tf32(e[t], hf, lo);
        char* p = tb + (lbase + t) * 16 + r4;
        *(float*)p = hf;
        *(float*)(p + 8) = lo;
    }
}

// ---- shared gating routine (verified round-2 logic), returns mingap ----
__device__ __forceinline__ float do_gate(const float* row, float* outIdx,
                                         float* outW, size_t base) {
    float gmax[NGROUP];
    float m = NEG_INF;
#pragma unroll
    for (int g = 0; g < NGROUP; g++) {
        float gm = NEG_INF;
#pragma unroll
        for (int j = 0; j < EPG; j++)
            gm = fmaxf(gm, row[g * EPG + j]);
        gmax[g] = gm;
        m = fmaxf(m, gm);
    }

    float v0 = NEG_INF, v1 = NEG_INF, v2 = NEG_INF;
    int g0 = 0, g1 = 0, g2 = 0;
#pragma unroll
    for (int g = 0; g < NGROUP; g++) {
        const float v = gmax[g];
        if (v > v0)      { v2 = v1; g2 = g1; v1 = v0; g1 = g0; v0 = v; g0 = g; }
        else if (v > v1) { v2 = v1; g2 = g1; v1 = v;  g1 = g; }
        else if (v > v2) { v2 = v;  g2 = g; }
    }
    const unsigned gm_mask = (1u << g0) | (1u << g1) | (1u << g2);

    // 4th-best group max (margin for group selection)
    float v3 = NEG_INF;
#pragma unroll
    for (int g = 0; g < NGROUP; g++)
        if (!((gm_mask >> g) & 1u)) v3 = fmaxf(v3, gmax[g]);

    float tv0 = NEG_INF, tv1 = NEG_INF, tv2 = NEG_INF;
    float tv3 = NEG_INF, tv4 = NEG_INF, tv5 = NEG_INF;
    int ti0 = -1, ti1 = -1, ti2 = -1, ti3 = -1, ti4 = -1, ti5 = -1;
#pragma unroll 1
    for (int g = 0; g < NGROUP; g++) {
        if (!((gm_mask >> g) & 1u)) continue;
#pragma unroll 1
        for (int j = 0; j < EPG; j++) {
            const int e = g * EPG + j;
            const float v = row[e];
            if (v > tv5) {
                if (v > tv4) { tv5 = tv4; ti5 = ti4;
                    if (v > tv3) { tv4 = tv3; ti4 = ti3;
                        if (v > tv2) { tv3 = tv2; ti3 = ti2;
                            if (v > tv1) { tv2 = tv1; ti2 = ti1;
                                if (v > tv0) { tv1 = tv0; ti1 = ti0; tv0 = v; ti0 = e; }
                                else          { tv1 = v;  ti1 = e; }
                            } else { tv2 = v; ti2 = e; }
                        } else { tv3 = v; ti3 = e; }
                    } else { tv4 = v; ti4 = e; }
                } else { tv5 = v; ti5 = e; }
            }
        }
    }

    // 7th-best allowed expert (margin for rank-6/7)
    float tv6 = NEG_INF;
#pragma unroll 1
    for (int g = 0; g < NGROUP; g++) {
        if (!((gm_mask >> g) & 1u)) continue;
#pragma unroll 1
        for (int j = 0; j < EPG; j++) {
            const int e = g * EPG + j;
            const float v = row[e];
            if (v > tv6 &&
                e != ti0 && e != ti1 && e != ti2 &&
                e != ti3 && e != ti4 && e != ti5) tv6 = v;
        }
    }

    const float w0 = expf(tv0 - m), w1 = expf(tv1 - m), w2 = expf(tv2 - m);
    const float w3 = expf(tv3 - m), w4 = expf(tv4 - m), w5 = expf(tv5 - m);
    const float inv = 1.0f / (w0 + w1 + w2 + w3 + w4 + w5 + 1e-20f);

    outIdx[base + 0] = (float)ti0;  outW[base + 0] = w0 * inv;
    outIdx[base + 1] = (float)ti1;  outW[base + 1] = w1 * inv;
    outIdx[base + 2] = (float)ti2;  outW[base + 2] = w2 * inv;
    outIdx[base + 3] = (float)ti3;  outW[base + 3] = w3 * inv;
    outIdx[base + 4] = (float)ti4;  outW[base + 4] = w4 * inv;
    outIdx[base + 5] = (float)ti5;  outW[base + 5] = w5 * inv;

    // min decision margin
    float mg = v2 - v3;
    mg = fminf(mg, tv0 - tv1);
    mg = fminf(mg, tv1 - tv2);
    mg = fminf(mg, tv2 - tv3);
    mg = fminf(mg, tv3 - tv4);
    mg = fminf(mg, tv4 - tv5);
    mg = fminf(mg, tv5 - tv6);
    return mg;
}

extern "C" __global__ void reset_kernel() {
    if (threadIdx.x == 0 && blockIdx.x == 0) g_count = 0;
}

extern "C" __global__ void __launch_bounds__(NTHREADS, 1)
moe_gate_kernel(const float* __restrict__ X,
                const float* __restrict__ W,
                float* __restrict__ out, int T)
{
    extern __shared__ char smem[];
    float* logits = (float*)smem;

    const int tid  = threadIdx.x;
    const int wid  = tid >> 5;
    const int lane = tid & 31;
    const int wm   = wid >> 2;
    const int wn   = wid & 3;
    const int row0 = blockIdx.x * BM;

    float acc[4][5][4];
#pragma unroll
    for (int i = 0; i < 4; i++)
#pragma unroll
        for (int j = 0; j < 5; j++)
#pragma unroll
            for (int r = 0; r < 4; r++) acc[i][j][r] = 0.0f;

    const int a0r = tid >> 2,          a0q = tid & 3;
    const int a1r = (tid + 256) >> 2,  a1q = (tid + 256) & 3;
    const int b0r = tid >> 2,          b0q = tid & 3;
    const int b1r = (tid + 256) >> 2,  b1q = (tid + 256) & 3;
    const int b2r = (tid + 512) >> 2,  b2q = (tid + 512) & 3;
    const bool bp2 = (tid < 128);

    const float* Ap0 = X + (size_t)(row0 + a0r) * HIDDEN + a0q * 4;
    const float* Ap1 = X + (size_t)(row0 + a1r) * HIDDEN + a1q * 4;
    const float* Bp0 = W + (size_t)b0r * HIDDEN + b0q * 4;
    const float* Bp1 = W + (size_t)b1r * HIDDEN + b1q * 4;
    const float* Bp2 = W + (size_t)b2r * HIDDEN + b2q * 4;

    float4 fa0, fa1, fb0, fb1, fb2;
    fb2 = make_float4(0.f, 0.f, 0.f, 0.f);

    fa0 = *(const float4*)(Ap0);
    fa1 = *(const float4*)(Ap1);
    fb0 = *(const float4*)(Bp0);
    fb1 = *(const float4*)(Bp1);
    if (bp2) fb2 = *(const float4*)(Bp2);

    for (int c = 0; c < NCHUNK; ++c) {
        char* buf = smem + (c & 1) * CHUNK_BYTES;

        stage_f4A(buf, a0r, a0q, fa0);
        stage_f4A(buf, a1r, a1q, fa1);
        stage_f4B(buf, b0r, b0q, fb0);
        stage_f4B(buf, b1r, b1q, fb1);
        if (bp2) stage_f4B(buf, b2r, b2q, fb2);
        __syncthreads();

        if (c + 1 < NCHUNK) {
            const int k0 = (c + 1) * BK;
            fa0 = *(const float4*)(Ap0 + k0);
            fa1 = *(const float4*)(Ap1 + k0);
            fb0 = *(const float4*)(Bp0 + k0);
            fb1 = *(const float4*)(Bp1 + k0);
            if (bp2) fb2 = *(const float4*)(Bp2 + k0);
        }

#pragma unroll
        for (int h = 0; h < 2; h++) {
            const char* ab = buf + h * A_HALF;
            const char* bb = buf + A_BYTES + h * B_HALF;

            uint4 bf[5];
#pragma unroll
            for (int j = 0; j < 5; j++)
                bf[j] = *(const uint4*)(bb + (wn * 5 + j) * 512 + lane * 16);

#pragma unroll
            for (int i = 0; i < 4; i++) {
                const char* tb = ab + (wm * 4 + i) * 1024 + lane * 16;
                const uint4 ah = *(const uint4*)(tb);
                const uint4 al = *(const uint4*)(tb + 512);
                const uint32_t ahr[4] = {ah.x, ah.y, ah.z, ah.w};
                const uint32_t alr[4] = {al.x, al.y, al.z, al.w};
#pragma unroll
                for (int j = 0; j < 5; j++) {
                    mma_tf32(acc[i][j], ahr, bf[j].x, bf[j].y);
                    mma_tf32(acc[i][j], ahr, bf[j].z, bf[j].w);
                    mma_tf32(acc[i][j], alr, bf[j].x, bf[j].y);
                }
            }
        }
    }

    __syncthreads();
    {
        const int g = lane >> 2, t = lane & 3;
#pragma unroll
        for (int i = 0; i < 4; i++) {
#pragma unroll
            for (int j = 0; j < 5; j++) {
                float* lrow = logits + (wm * 64 + i * 16 + g) * LSTR
                                     + wn * 40 + j * 8 + t * 2;
                lrow[0] = acc[i][j][0];
                lrow[1] = acc[i][j][1];
                lrow[8 * LSTR + 0] = acc[i][j][2];
                lrow[8 * LSTR + 1] = acc[i][j][3];
            }
        }
    }
    __syncthreads();

    if (tid < BM) {
        const int t = row0 + tid;
        if (t < T) {
            const float mg = do_gate(logits + tid * LSTR,
                                     out, out + (size_t)T * TOPK,
                                     (size_t)t * TOPK);
            if (mg < DELTA) {
                const int slot = atomicAdd(&g_count, 1);
                g_list[slot] = t;
            }
        }
    }
}

// ---- rescue pass: exact serial-fp32 recompute for flagged tokens ----
extern "C" __global__ void __launch_bounds__(256, 1)
refine_kernel(const float* __restrict__ X,
              const float* __restrict__ W,
              float* __restrict__ out, int T)
{
    __shared__ float xs[HIDDEN];
    __shared__ float lg[NEXP];

    const int count = g_count;
    for (int i = blockIdx.x; i < count; i += gridDim.x) {
        const int t = g_list[i];
        const float* xr = X + (size_t)t * HIDDEN;
        for (int k = threadIdx.x; k < HIDDEN; k += blockDim.x)
            xs[k] = xr[k];
        __syncthreads();

        if (threadIdx.x < NEXP) {
            const float* wr = W + (size_t)threadIdx.x * HIDDEN;
            float acc = 0.0f;
#pragma unroll 8
            for (int k = 0; k < HIDDEN; k++) {
                // strict serial ascending-k fma.rn (matches verified round-2 path)
                asm("fma.rn.f32 %0, %1, %2, %0;"
                    : "+f"(acc) : "f"(xs[k]), "f"(wr[k]));
            }
            lg[threadIdx.x] = acc;
        }
        __syncthreads();

        if (threadIdx.x == 0) {
            do_gate(lg, out, out + (size_t)T * TOPK, (size_t)t * TOPK);
        }
        __syncthreads();
    }
}

extern "C" void kernel_launch(void* const* d_in, const int* in_sizes, int n_in,
                              void* d_out, int out_size)
{
    const float* X = (const float*)d_in[0];
    const float* W = (const float*)d_in[1];
    const int T = in_sizes[0] / HIDDEN;   // 16384

    cudaFuncSetAttribute(moe_gate_kernel,
                         cudaFuncAttributeMaxDynamicSharedMemorySize, SMEM_BYTES);

    reset_kernel<<<1, 32>>>();
    const int grid = (T + BM - 1) / BM;   // 128
    moe_gate_kernel<<<grid, NTHREADS, SMEM_BYTES>>>(X, W, (float*)d_out, T);
    refine_kernel<<<148, 256>>>(X, W, (float*)d_out, T);
}